// round 16
// baseline (speedup 1.0000x reference)
#include <cuda_runtime.h>
#include <cstdint>

#define NCBK   8
#define KC     1024
#define CDIM   64
#define TSEQQ  2048
#define DDIM   512
#define NTOKN  16384
#define MT     64
#define THREADS 256
#define TOTCH  64          // 8 stages * 8 chunks of 128 codes

// smem: 2 x 32KB B ring + 2 x 512B cbn + 2 x 1KB top2 exchange
#define SM_CBN   65536u
#define SM_EX    66560u
#define SM_TOTAL 68608

// Codebook B fragments: per chunk two 16KB halves; within half h, pairs are
// (c, c+32). hi tf32 only.
__device__ __align__(128) float g_Bfrag[TOTCH * 8192];
__device__ __align__(128) float g_cbnC[TOTCH * 128];

__device__ __forceinline__ float f2tff(float v) {
    uint32_t r; asm("cvt.rna.tf32.f32 %0,%1;" : "=r"(r) : "f"(v));
    return __uint_as_float(r);
}
__device__ __forceinline__ uint32_t smem_u32(const void* p) {
    uint32_t a;
    asm("{ .reg .u64 t; cvta.to.shared.u64 t,%1; cvt.u32.u64 %0,t; }" : "=r"(a) : "l"(p));
    return a;
}
__device__ __forceinline__ void cpa16(uint32_t d, const void* s) {
    asm volatile("cp.async.cg.shared.global [%0],[%1],16;" :: "r"(d), "l"(s));
}
__device__ __forceinline__ void cp_commit() { asm volatile("cp.async.commit_group;" ::: "memory"); }
__device__ __forceinline__ void cp_wait0()  { asm volatile("cp.async.wait_group 0;" ::: "memory"); }

__device__ __forceinline__ float2 lds64(uint32_t a) {
    float2 v;
    asm volatile("ld.shared.v2.f32 {%0,%1},[%2];" : "=f"(v.x), "=f"(v.y) : "r"(a));
    return v;
}
__device__ __forceinline__ float4 lds128(uint32_t a) {
    float4 v;
    asm volatile("ld.shared.v4.f32 {%0,%1,%2,%3},[%4];"
                 : "=f"(v.x), "=f"(v.y), "=f"(v.z), "=f"(v.w) : "r"(a));
    return v;
}
__device__ __forceinline__ void sts64u(uint32_t a, uint32_t x, uint32_t y) {
    asm volatile("st.shared.v2.u32 [%0],{%1,%2};" :: "r"(a), "r"(x), "r"(y));
}
__device__ __forceinline__ uint2 lds64u(uint32_t a) {
    uint2 v;
    asm volatile("ld.shared.v2.u32 {%0,%1},[%2];" : "=r"(v.x), "=r"(v.y) : "r"(a));
    return v;
}

__device__ __forceinline__ void mma8(float c[4], const float a[4], float b0, float b1) {
    asm volatile(
        "mma.sync.aligned.m16n8k8.row.col.f32.tf32.tf32.f32 "
        "{%0,%1,%2,%3},{%4,%5,%6,%7},{%8,%9},{%0,%1,%2,%3};"
        : "+f"(c[0]), "+f"(c[1]), "+f"(c[2]), "+f"(c[3])
        : "r"(__float_as_uint(a[0])), "r"(__float_as_uint(a[1])),
          "r"(__float_as_uint(a[2])), "r"(__float_as_uint(a[3])),
          "r"(__float_as_uint(b0)), "r"(__float_as_uint(b1)));
}

// ---- branchless 32-bit packed top-2 ----
__device__ __forceinline__ uint32_t packkey(float k, int idx) {
    uint32_t u = __float_as_uint(k);
    u ^= (uint32_t)(((int32_t)u) >> 31) | 0x80000000u;
    return (u & 0xFFFFFC00u) | (uint32_t)idx;
}
__device__ __forceinline__ void t2u(uint32_t& m1, uint32_t& m2, uint32_t p) {
    const uint32_t hi = umax(m1, p);
    m1 = umin(m1, p);
    m2 = umin(m2, hi);
}
__device__ __forceinline__ void t2merge(uint32_t& m1, uint32_t& m2,
                                        uint32_t o1, uint32_t o2) {
    const uint32_t hi = umax(m1, o1);
    m1 = umin(m1, o1);
    m2 = umin(umin(m2, o2), hi);
}

#define BETTER(av, ak, bv, bk) ((av) < (bv) || ((av) == (bv) && (ak) < (bk)))

// ---------------- prep: half-split paired hi-tf32 B fragments + norms --------
// Per chunk 32KB = 2048 float4: u = h*1024 + ks*128 + pair*32 + t.
// float4 = { B(c0,d), B(c0,d+4), B(c1,d), B(c1,d+4) }
// c0 = cbase + h*64 + pair*8 + (t>>2), c1 = c0 + 32, d = ks*8 + (t&3).
__global__ void prep(const float* __restrict__ cb) {
    const int chunk = blockIdx.x;
    const int i = chunk >> 3, kb = chunk & 7;
    const float* cbs = cb + (size_t)i * KC * CDIM;
    const int cbase = kb * 128;
    float4* dsth = (float4*)(g_Bfrag + (size_t)chunk * 8192);
    for (int u = threadIdx.x; u < 2048; u += blockDim.x) {
        const int h = u >> 10, ks = (u >> 7) & 7, pair = (u >> 5) & 3, t = u & 31;
        const int c0 = cbase + h * 64 + pair * 8 + (t >> 2);
        const int c1 = c0 + 32;
        const int d = ks * 8 + (t & 3);
        dsth[u] = make_float4(f2tff(cbs[c0 * CDIM + d]),
                              f2tff(cbs[c0 * CDIM + d + 4]),
                              f2tff(cbs[c1 * CDIM + d]),
                              f2tff(cbs[c1 * CDIM + d + 4]));
    }
    if (threadIdx.x < 128) {
        const int code = cbase + threadIdx.x;
        float s = 0.f;
        #pragma unroll
        for (int d = 0; d < CDIM; d++) { const float v = cbs[code * CDIM + d]; s += v * v; }
        g_cbnC[chunk * 128 + threadIdx.x] = s;
    }
}

// ---------------- main: 8 warps/CTA, N-split warp pairs ----------------------
__global__ void __launch_bounds__(THREADS, 2)
rvq_main(const float* __restrict__ z, const float* __restrict__ cbooks,
         float* __restrict__ outZq, float* __restrict__ outIdx,
         float* __restrict__ outLogits)
{
    extern __shared__ __align__(16) char sm[];
    const uint32_t smb = smem_u32(sm);

    const int tid = threadIdx.x;
    const int w = tid >> 5, t = tid & 31;
    const int wr = w & 3, wc = w >> 2;        // row group / column half
    const int q = t & 3, g = t >> 2;

    const int tokBase = blockIdx.x * MT;
    const int rowA = wr * 16 + g;
    const int rowB = rowA + 8;
    const int tokA = tokBase + rowA, tokB = tokBase + rowB;
    const int bA = tokA >> 11, tlA = tokA & (TSEQQ - 1);
    const int bB = tokB >> 11, tlB = tokB & (TSEQQ - 1);

    const float* zA = z + (size_t)tokA * DDIM;
    const float* zB = z + (size_t)tokB * DDIM;

    // ares = exact fp32 residual (duplicated across wc pairs; deterministic)
    float ares[8][4];
    float rn0 = 0.f, rn1 = 0.f;
    #pragma unroll
    for (int m = 0; m < 16; m++) {
        const int d = 4 * m + q, ks = m >> 1, p = (m & 1) * 2;
        const float vA = zA[d], vB = zB[d];
        rn0 += vA * vA; rn1 += vB * vB;
        ares[ks][p]     = vA;
        ares[ks][p + 1] = vB;
    }
    rn0 += __shfl_xor_sync(0xffffffffu, rn0, 1); rn0 += __shfl_xor_sync(0xffffffffu, rn0, 2);
    rn1 += __shfl_xor_sync(0xffffffffu, rn1, 1); rn1 += __shfl_xor_sync(0xffffffffu, rn1, 2);

    // prologue prefetch: chunk 0 into ring slot 0 (2048 float4 / 256 thr)
    {
        const char* src = (const char*)g_Bfrag;
        #pragma unroll
        for (int j = 0; j < 8; j++)
            cpa16(smb + (uint32_t)(tid + j * 256) * 16u, src + (size_t)(tid + j * 256) * 16);
        if (tid < 32)
            cpa16(smb + SM_CBN + (uint32_t)tid * 16u, (const char*)g_cbnC + tid * 16);
        cp_commit();
    }

    for (int i = 0; i < NCBK; i++) {
        uint32_t m1A = 0xFFFFFFFFu, m2A = 0xFFFFFFFFu;   // rowA packed top-2 (this half)
        uint32_t m1B = 0xFFFFFFFFu, m2B = 0xFFFFFFFFu;   // rowB packed top-2

        float* lgA = outLogits + ((size_t)(bA * NCBK + i) * TSEQQ + tlA) * KC;
        float* lgB = outLogits + ((size_t)(bB * NCBK + i) * TSEQQ + tlB) * KC;

        for (int kb = 0; kb < 8; kb++) {
            const int s = i * 8 + kb;
            const int buf = s & 1;

            cp_wait0();        // B[buf] (prefetched at step s-1) locally done
            __syncthreads();   // publish B[buf]; orders step s-1 readers of
                               // buf^1 before its refill below

            if (s + 1 < TOTCH) {
                const int nb = buf ^ 1;
                const char* src = (const char*)(g_Bfrag + (size_t)(s + 1) * 8192);
                #pragma unroll
                for (int j = 0; j < 8; j++)
                    cpa16(smb + (uint32_t)nb * 32768u + (uint32_t)(tid + j * 256) * 16u,
                          src + (size_t)(tid + j * 256) * 16);
                if (tid < 32)
                    cpa16(smb + SM_CBN + (uint32_t)nb * 512u + (uint32_t)tid * 16u,
                          (const char*)(g_cbnC + (s + 1) * 128) + tid * 16);
                cp_commit();
            }

            // ---- MMA: 1-pass tf32(A) x Bhi, this warp's 64-col half ----
            float acc[8][4];
            #pragma unroll
            for (int nt = 0; nt < 8; nt++)
                #pragma unroll
                for (int v = 0; v < 4; v++) acc[nt][v] = 0.f;

            const uint32_t bbase = smb + (uint32_t)buf * 32768u
                                 + (uint32_t)wc * 16384u + (uint32_t)t * 16u;
            #pragma unroll
            for (int ks = 0; ks < 8; ks++) {
                float af[4];
                af[0] = f2tff(ares[ks][0]);
                af[1] = f2tff(ares[ks][1]);
                af[2] = f2tff(ares[ks][2]);
                af[3] = f2tff(ares[ks][3]);
                const uint32_t kbase = bbase + (uint32_t)(ks * 2048);
                #pragma unroll
                for (int j = 0; j < 4; j++) {
                    const float4 bp = lds128(kbase + (uint32_t)(j * 512));
                    mma8(acc[j],     af, bp.x, bp.y);
                    mma8(acc[j + 4], af, bp.z, bp.w);
                }
            }

            // ---- epilogue: top-2 + direct logit stores (sector-aligned) ----
            const uint32_t cbb = smb + SM_CBN + (uint32_t)buf * 512u;
            #pragma unroll
            for (int jj = 0; jj < 8; jj++) {
                const int col = wc * 64 + (jj >> 2) * 32 + (jj & 3) * 8 + 2 * q;
                const float2 cn = lds64(cbb + (uint32_t)col * 4u);
                const float kA0 = cn.x - 2.f * acc[jj][0];
                const float kA1 = cn.y - 2.f * acc[jj][1];
                const float kB0 = cn.x - 2.f * acc[jj][2];
                const float kB1 = cn.y - 2.f * acc[jj][3];
                const int kidx = kb * 128 + col;
                t2u(m1A, m2A, packkey(kA0, kidx));
                t2u(m1A, m2A, packkey(kA1, kidx + 1));
                t2u(m1B, m2B, packkey(kB0, kidx));
                t2u(m1B, m2B, packkey(kB1, kidx + 1));
                *(float2*)(lgA + kb * 128 + col) = make_float2(-kA0 - rn0, -kA1 - rn0);
                *(float2*)(lgB + kb * 128 + col) = make_float2(-kB0 - rn1, -kB1 - rn1);
            }
        }

        // ---- stage end: quad merge, then cross-half merge via smem ----
        #pragma unroll
        for (int x = 1; x <= 2; x <<= 1) {
            const uint32_t o1A = __shfl_xor_sync(0xffffffffu, m1A, x);
            const uint32_t o2A = __shfl_xor_sync(0xffffffffu, m2A, x);
            t2merge(m1A, m2A, o1A, o2A);
            const uint32_t o1B = __shfl_xor_sync(0xffffffffu, m1B, x);
            const uint32_t o2B = __shfl_xor_sync(0xffffffffu, m2B, x);
            t2merge(m1B, m2B, o1B, o2B);
        }
        // exchange buffers double-buffered by stage parity; the write below is
        // ordered after the partner's previous-same-parity read by the 8 chunk
        // barriers of the intervening stage.
        const uint32_t exb = smb + SM_EX + (uint32_t)(i & 1) * 1024u;
        if (q == 0) {
            sts64u(exb + (uint32_t)(wc * 512 + rowA * 8), m1A, m2A);
            sts64u(exb + (uint32_t)(wc * 512 + rowB * 8), m1B, m2B);
        }
        __syncthreads();
        {
            const uint2 pA = lds64u(exb + (uint32_t)((wc ^ 1) * 512 + rowA * 8));
            t2merge(m1A, m2A, pA.x, pA.y);
            const uint2 pB = lds64u(exb + (uint32_t)((wc ^ 1) * 512 + rowB * 8));
            t2merge(m1B, m2B, pB.x, pB.y);
        }
        const int bk0 = (int)(m1A & 0x3FFu);
        const int bk1 = (int)(m2A & 0x3FFu);
        const int ck0 = (int)(m1B & 0x3FFu);
        const int ck1 = (int)(m2B & 0x3FFu);

        // ---- exact fp32 rescore of both candidates per row (dup across wc) ----
        const float* cbi = cbooks + (size_t)i * KC * CDIM;
        float pdA1 = 0.f, pnA1 = 0.f, pdA2 = 0.f, pnA2 = 0.f;
        float pdB1 = 0.f, pnB1 = 0.f, pdB2 = 0.f, pnB2 = 0.f;
        #pragma unroll
        for (int m = 0; m < 16; m++) {
            const int d = 4 * m + q, ks = m >> 1, p = (m & 1) * 2;
            const float rA = ares[ks][p];
            const float rB = ares[ks][p + 1];
            float cvv;
            cvv = __ldg(cbi + (size_t)bk0 * CDIM + d); pdA1 += rA * cvv; pnA1 += cvv * cvv;
            cvv = __ldg(cbi + (size_t)bk1 * CDIM + d); pdA2 += rA * cvv; pnA2 += cvv * cvv;
            cvv = __ldg(cbi + (size_t)ck0 * CDIM + d); pdB1 += rB * cvv; pnB1 += cvv * cvv;
            cvv = __ldg(cbi + (size_t)ck1 * CDIM + d); pdB2 += rB * cvv; pnB2 += cvv * cvv;
        }
        #pragma unroll
        for (int x = 1; x <= 2; x <<= 1) {
            pdA1 += __shfl_xor_sync(0xffffffffu, pdA1, x);
            pnA1 += __shfl_xor_sync(0xffffffffu, pnA1, x);
            pdA2 += __shfl_xor_sync(0xffffffffu, pdA2, x);
            pnA2 += __shfl_xor_sync(0xffffffffu, pnA2, x);
            pdB1 += __shfl_xor_sync(0xffffffffu, pdB1, x);
            pnB1 += __shfl_xor_sync(0xffffffffu, pnB1, x);
            pdB2 += __shfl_xor_sync(0xffffffffu, pdB2, x);
            pnB2 += __shfl_xor_sync(0xffffffffu, pnB2, x);
        }
        const float keyA1 = pnA1 - 2.f * pdA1, keyA2 = pnA2 - 2.f * pdA2;
        const float keyB1 = pnB1 - 2.f * pdB1, keyB2 = pnB2 - 2.f * pdB2;
        const int selA = BETTER(keyA2, bk1, keyA1, bk0) ? bk1 : bk0;
        const int selB = BETTER(keyB2, ck1, keyB1, ck0) ? ck1 : ck0;

        if (q == 0 && wc == 0) {
            outIdx[(size_t)(bA * NCBK + i) * TSEQQ + tlA] = (float)selA;
            outIdx[(size_t)(bB * NCBK + i) * TSEQQ + tlB] = (float)selB;
        }

        // ---- gather q, write z_q (wc=0 only), residual update (all) ----
        const float* qp0 = cbi + (size_t)selA * CDIM;
        const float* qp1 = cbi + (size_t)selB * CDIM;
        float* zqA = outZq + (size_t)tokA * DDIM + i * CDIM;
        float* zqB = outZq + (size_t)tokB * DDIM + i * CDIM;
        float nr0 = 0.f, nr1 = 0.f;
        #pragma unroll
        for (int m = 0; m < 16; m++) {
            const int d = 4 * m + q, ks = m >> 1, p = (m & 1) * 2;
            const float q0 = __ldg(qp0 + d), q1 = __ldg(qp1 + d);
            if (wc == 0) { zqA[d] = q0; zqB[d] = q1; }
            if (i < NCBK - 1) {
                const float vA = zA[(i + 1) * CDIM + d] + ares[ks][p] - q0;
                const float vB = zB[(i + 1) * CDIM + d] + ares[ks][p + 1] - q1;
                nr0 += vA * vA; nr1 += vB * vB;
                ares[ks][p]     = vA;
                ares[ks][p + 1] = vB;
            }
        }
        if (i < NCBK - 1) {
            nr0 += __shfl_xor_sync(0xffffffffu, nr0, 1);
            nr0 += __shfl_xor_sync(0xffffffffu, nr0, 2);
            nr1 += __shfl_xor_sync(0xffffffffu, nr1, 1);
            nr1 += __shfl_xor_sync(0xffffffffu, nr1, 2);
            rn0 = nr0; rn1 = nr1;
        }
    }
}

extern "C" void kernel_launch(void* const* d_in, const int* in_sizes, int n_in,
                              void* d_out, int out_size) {
    const float* z      = (const float*)d_in[0];   // (8, 2048, 512) f32
    const float* cbooks = (const float*)d_in[1];   // (8, 1024, 64)  f32

    float* outZq     = (float*)d_out;
    float* outIdx    = outZq + (size_t)NTOKN * DDIM;
    float* outLogits = outIdx + (size_t)NCBK * NTOKN;

    cudaFuncSetAttribute(rvq_main, cudaFuncAttributeMaxDynamicSharedMemorySize, SM_TOTAL);

    prep<<<TOTCH, 256>>>(cbooks);
    rvq_main<<<NTOKN / MT, THREADS, SM_TOTAL>>>(z, cbooks, outZq, outIdx, outLogits);
}

// round 17
// speedup vs baseline: 1.1221x; 1.1221x over previous
#include <cuda_runtime.h>
#include <cstdint>

#define NCBK   8
#define KC     1024
#define CDIM   64
#define TSEQQ  2048
#define DDIM   512
#define NTOKN  16384
#define MT     64
#define THREADS 128
#define TOTCH  64          // 8 stages * 8 chunks of 128 codes

// smem: 3 x 32KB B ring + 3 x 512B cbn ring
#define SM_CBN   98304u
#define SM_TOTAL 99840

// Codebook B fragments (paired m16n8k8 layout), hi tf32 only, 32KB per chunk
__device__ __align__(128) float g_Bfrag[TOTCH * 8192];
__device__ __align__(128) float g_cbnC[TOTCH * 128];

__device__ __forceinline__ uint32_t f2tf(float v) {
    uint32_t r; asm("cvt.rna.tf32.f32 %0,%1;" : "=r"(r) : "f"(v)); return r;
}
__device__ __forceinline__ float f2tff(float v) {
    uint32_t r; asm("cvt.rna.tf32.f32 %0,%1;" : "=r"(r) : "f"(v));
    return __uint_as_float(r);
}
__device__ __forceinline__ uint32_t smem_u32(const void* p) {
    uint32_t a;
    asm("{ .reg .u64 t; cvta.to.shared.u64 t,%1; cvt.u32.u64 %0,t; }" : "=r"(a) : "l"(p));
    return a;
}
__device__ __forceinline__ void cpa16(uint32_t d, const void* s) {
    asm volatile("cp.async.cg.shared.global [%0],[%1],16;" :: "r"(d), "l"(s));
}
__device__ __forceinline__ void cp_commit() { asm volatile("cp.async.commit_group;" ::: "memory"); }
__device__ __forceinline__ void cp_wait1()  { asm volatile("cp.async.wait_group 1;" ::: "memory"); }
__device__ __forceinline__ void cp_wait0()  { asm volatile("cp.async.wait_group 0;" ::: "memory"); }

__device__ __forceinline__ float2 lds64(uint32_t a) {
    float2 v;
    asm volatile("ld.shared.v2.f32 {%0,%1},[%2];" : "=f"(v.x), "=f"(v.y) : "r"(a));
    return v;
}
__device__ __forceinline__ float4 lds128(uint32_t a) {
    float4 v;
    asm volatile("ld.shared.v4.f32 {%0,%1,%2,%3},[%4];"
                 : "=f"(v.x), "=f"(v.y), "=f"(v.z), "=f"(v.w) : "r"(a));
    return v;
}

__device__ __forceinline__ void mma8(float c[4], const float a[4], float b0, float b1) {
    asm volatile(
        "mma.sync.aligned.m16n8k8.row.col.f32.tf32.tf32.f32 "
        "{%0,%1,%2,%3},{%4,%5,%6,%7},{%8,%9},{%0,%1,%2,%3};"
        : "+f"(c[0]), "+f"(c[1]), "+f"(c[2]), "+f"(c[3])
        : "r"(__float_as_uint(a[0])), "r"(__float_as_uint(a[1])),
          "r"(__float_as_uint(a[2])), "r"(__float_as_uint(a[3])),
          "r"(__float_as_uint(b0)), "r"(__float_as_uint(b1)));
}

// ---- branchless 32-bit packed top-2 ----
__device__ __forceinline__ uint32_t packkey(float k, int idx) {
    uint32_t u = __float_as_uint(k);
    u ^= (uint32_t)(((int32_t)u) >> 31) | 0x80000000u;
    return (u & 0xFFFFFC00u) | (uint32_t)idx;
}
__device__ __forceinline__ void t2u(uint32_t& m1, uint32_t& m2, uint32_t p) {
    const uint32_t hi = umax(m1, p);
    m1 = umin(m1, p);
    m2 = umin(m2, hi);
}
__device__ __forceinline__ void t2merge(uint32_t& m1, uint32_t& m2,
                                        uint32_t o1, uint32_t o2) {
    const uint32_t hi = umax(m1, o1);
    m1 = umin(m1, o1);
    m2 = umin(umin(m2, o2), hi);
}

#define BETTER(av, ak, bv, bk) ((av) < (bv) || ((av) == (bv) && (ak) < (bk)))

// ---------------- prep: pack codebooks as hi-tf32 B fragments + exact norms ----
// Layout per chunk (32KB = 2048 float4): u = ks*256 + pair*32 + t.
// float4 = { B(code0,d), B(code0,d+4), B(code1,d), B(code1,d+4) }
// with code0 = pair*8 + t/4, code1 = code0 + 64, d = ks*8 + (t&3).
// 4 CTAs per chunk (full-chip parallelism): part = bid&3 covers u in
// [part*512, part*512+512) and codes [part*32, part*32+32) for norms.
__global__ void prep(const float* __restrict__ cb) {
    const int blk = blockIdx.x;              // 0..255
    const int chunk = blk >> 2, part = blk & 3;
    const int i = chunk >> 3, kb = chunk & 7;
    const float* cbs = cb + (size_t)i * KC * CDIM;
    const int cbase = kb * 128;
    float4* dsth = (float4*)(g_Bfrag + (size_t)chunk * 8192);
    #pragma unroll
    for (int r = 0; r < 2; r++) {
        const int u = part * 512 + r * 256 + threadIdx.x;
        const int ks = u >> 8, pair = (u >> 5) & 7, t = u & 31;
        const int code0 = cbase + pair * 8 + (t >> 2);
        const int code1 = code0 + 64;
        const int d = ks * 8 + (t & 3);
        dsth[u] = make_float4(f2tff(cbs[code0 * CDIM + d]),
                              f2tff(cbs[code0 * CDIM + d + 4]),
                              f2tff(cbs[code1 * CDIM + d]),
                              f2tff(cbs[code1 * CDIM + d + 4]));
    }
    if (threadIdx.x < 32) {
        const int code = cbase + part * 32 + threadIdx.x;
        float s = 0.f;
        #pragma unroll
        for (int d = 0; d < CDIM; d++) { const float v = cbs[code * CDIM + d]; s += v * v; }
        g_cbnC[chunk * 128 + part * 32 + threadIdx.x] = s;
    }
}

// ---------------- main (2 CTAs / SM, 3-buffer ring, direct logit STG) -------
__global__ void __launch_bounds__(THREADS, 2)
rvq_main(const float* __restrict__ z, const float* __restrict__ cbooks,
         float* __restrict__ outZq, float* __restrict__ outIdx,
         float* __restrict__ outLogits)
{
    extern __shared__ __align__(16) char sm[];
    const uint32_t smb = smem_u32(sm);

    const int tid = threadIdx.x;
    const int w = tid >> 5, t = tid & 31;     // w in 0..3
    const int q = t & 3, g = t >> 2;

    const int tokBase = blockIdx.x * MT;
    const int off = (blockIdx.x & 1) * 4;     // chunk-order phase skew
    const int rowA = w * 16 + g;
    const int rowB = rowA + 8;
    const int tokA = tokBase + rowA, tokB = tokBase + rowB;
    const int bA = tokA >> 11, tlA = tokA & (TSEQQ - 1);
    const int bB = tokB >> 11, tlB = tokB & (TSEQQ - 1);

    const float* zA = z + (size_t)tokA * DDIM;
    const float* zB = z + (size_t)tokB * DDIM;

    // ares = exact fp32 residual; ahi = tf32 MMA fragments (round of ares)
    float ares[8][4], ahi[8][4];
    float rn0 = 0.f, rn1 = 0.f;
    #pragma unroll
    for (int m = 0; m < 16; m++) {
        const int d = 4 * m + q, ks = m >> 1, p = (m & 1) * 2;
        const float vA = zA[d], vB = zB[d];
        rn0 += vA * vA; rn1 += vB * vB;
        ares[ks][p]     = vA;
        ares[ks][p + 1] = vB;
        ahi[ks][p]      = f2tff(vA);
        ahi[ks][p + 1]  = f2tff(vB);
    }
    rn0 += __shfl_xor_sync(0xffffffffu, rn0, 1); rn0 += __shfl_xor_sync(0xffffffffu, rn0, 2);
    rn1 += __shfl_xor_sync(0xffffffffu, rn1, 1); rn1 += __shfl_xor_sync(0xffffffffu, rn1, 2);

    // prologue prefetch: first chunk (stage 0, kb=off) into ring slot 0
    {
        const char* src = (const char*)(g_Bfrag + (size_t)off * 8192);
        #pragma unroll
        for (int j = 0; j < 16; j++)
            cpa16(smb + (uint32_t)(tid + j * 128) * 16u, src + (size_t)(tid + j * 128) * 16);
        if (tid < 32)
            cpa16(smb + SM_CBN + (uint32_t)tid * 16u,
                  (const char*)(g_cbnC + off * 128) + tid * 16);
        cp_commit();
    }

    for (int i = 0; i < NCBK; i++) {
        uint32_t m1A = 0xFFFFFFFFu, m2A = 0xFFFFFFFFu;   // rowA packed top-2
        uint32_t m1B = 0xFFFFFFFFu, m2B = 0xFFFFFFFFu;   // rowB packed top-2

        float* lgA = outLogits + ((size_t)(bA * NCBK + i) * TSEQQ + tlA) * KC;
        float* lgB = outLogits + ((size_t)(bB * NCBK + i) * TSEQQ + tlB) * KC;

        for (int kk = 0; kk < 8; kk++) {
            const int s = i * 8 + kk;          // linear schedule position
            const int kb = (kk + off) & 7;     // actual chunk within stage
            const int buf = s % 3;

            // prefetch B[s+1] into ring slot (s+1)%3; its last readers (step
            // s-2) are ordered before this write by the barrier at step s-1.
            if (s + 1 < TOTCH) {
                const int nb = (s + 1) % 3;
                const int i2 = (s + 1) >> 3;
                const int kb2 = (((s + 1) & 7) + off) & 7;
                const int cn = i2 * 8 + kb2;
                const char* src = (const char*)(g_Bfrag + (size_t)cn * 8192);
                #pragma unroll
                for (int j = 0; j < 16; j++)
                    cpa16(smb + (uint32_t)nb * 32768u + (uint32_t)(tid + j * 128) * 16u,
                          src + (size_t)(tid + j * 128) * 16);
                if (tid < 32)
                    cpa16(smb + SM_CBN + (uint32_t)nb * 512u + (uint32_t)tid * 16u,
                          (const char*)(g_cbnC + cn * 128) + tid * 16);
                cp_commit();
                cp_wait1();
            } else {
                cp_wait0();
            }
            __syncthreads();   // B[buf]+cbn[buf] ready; all prior readers of
                               // ring slot (s+1)%3 have passed (see above)

            // ---- MMA: 1-pass Ahi x Bhi, 8 pairs x 8 k-steps, lds128 ----
            float acc[16][4];
            #pragma unroll
            for (int nt = 0; nt < 16; nt++)
                #pragma unroll
                for (int v = 0; v < 4; v++) acc[nt][v] = 0.f;

            const uint32_t bbase = smb + (uint32_t)buf * 32768u + (uint32_t)t * 16u;
            #pragma unroll
            for (int ks = 0; ks < 8; ks++) {
                const uint32_t kbase = bbase + (uint32_t)(ks * 4096);
                #pragma unroll
                for (int j = 0; j < 8; j++) {
                    const float4 bp = lds128(kbase + (uint32_t)(j * 512));
                    mma8(acc[j],     ahi[ks], bp.x, bp.y);
                    mma8(acc[j + 8], ahi[ks], bp.z, bp.w);
                }
            }

            // ---- epilogue: top-2 + direct logit stores (sector-aligned) ----
            const uint32_t cbb = smb + SM_CBN + (uint32_t)buf * 512u;
            const int colb = kb * 128 + 2 * q;
            #pragma unroll
            for (int nt = 0; nt < 16; nt++) {
                const float2 cn = lds64(cbb + (uint32_t)(nt * 8 + 2 * q) * 4u);
                const float kA0 = cn.x - 2.f * acc[nt][0];
                const float kA1 = cn.y - 2.f * acc[nt][1];
                const float kB0 = cn.x - 2.f * acc[nt][2];
                const float kB1 = cn.y - 2.f * acc[nt][3];
                const int kidx = kb * 128 + nt * 8 + 2 * q;
                t2u(m1A, m2A, packkey(kA0, kidx));
                t2u(m1A, m2A, packkey(kA1, kidx + 1));
                t2u(m1B, m2B, packkey(kB0, kidx));
                t2u(m1B, m2B, packkey(kB1, kidx + 1));
                *(float2*)(lgA + colb + nt * 8) = make_float2(-kA0 - rn0, -kA1 - rn0);
                *(float2*)(lgB + colb + nt * 8) = make_float2(-kB0 - rn1, -kB1 - rn1);
            }
        }

        // ---- stage end: quad merge of packed top-2 ----
        #pragma unroll
        for (int x = 1; x <= 2; x <<= 1) {
            const uint32_t o1A = __shfl_xor_sync(0xffffffffu, m1A, x);
            const uint32_t o2A = __shfl_xor_sync(0xffffffffu, m2A, x);
            t2merge(m1A, m2A, o1A, o2A);
            const uint32_t o1B = __shfl_xor_sync(0xffffffffu, m1B, x);
            const uint32_t o2B = __shfl_xor_sync(0xffffffffu, m2B, x);
            t2merge(m1B, m2B, o1B, o2B);
        }
        const int bk0 = (int)(m1A & 0x3FFu);
        const int bk1 = (int)(m2A & 0x3FFu);
        const int ck0 = (int)(m1B & 0x3FFu);
        const int ck1 = (int)(m2B & 0x3FFu);

        // ---- exact fp32 rescore of both candidates per row ----
        const float* cbi = cbooks + (size_t)i * KC * CDIM;
        float pdA1 = 0.f, pnA1 = 0.f, pdA2 = 0.f, pnA2 = 0.f;
        float pdB1 = 0.f, pnB1 = 0.f, pdB2 = 0.f, pnB2 = 0.f;
        #pragma unroll
        for (int m = 0; m < 16; m++) {
            const int d = 4 * m + q, ks = m >> 1, p = (m & 1) * 2;
            const float rA = ares[ks][p];
            const float rB = ares[ks][p + 1];
            float cvv;
            cvv = __ldg(cbi + (size_t)bk0 * CDIM + d); pdA1 += rA * cvv; pnA1 += cvv * cvv;
            cvv = __ldg(cbi + (size_t)bk1 * CDIM + d); pdA2 += rA * cvv; pnA2 += cvv * cvv;
            cvv = __ldg(cbi + (size_t)ck0 * CDIM + d); pdB1 += rB * cvv; pnB1 += cvv * cvv;
            cvv = __ldg(cbi + (size_t)ck1 * CDIM + d); pdB2 += rB * cvv; pnB2 += cvv * cvv;
        }
        #pragma unroll
        for (int x = 1; x <= 2; x <<= 1) {
            pdA1 += __shfl_xor_sync(0xffffffffu, pdA1, x);
            pnA1 += __shfl_xor_sync(0xffffffffu, pnA1, x);
            pdA2 += __shfl_xor_sync(0xffffffffu, pdA2, x);
            pnA2 += __shfl_xor_sync(0xffffffffu, pnA2, x);
            pdB1 += __shfl_xor_sync(0xffffffffu, pdB1, x);
            pnB1 += __shfl_xor_sync(0xffffffffu, pnB1, x);
            pdB2 += __shfl_xor_sync(0xffffffffu, pdB2, x);
            pnB2 += __shfl_xor_sync(0xffffffffu, pnB2, x);
        }
        const float keyA1 = pnA1 - 2.f * pdA1, keyA2 = pnA2 - 2.f * pdA2;
        const float keyB1 = pnB1 - 2.f * pdB1, keyB2 = pnB2 - 2.f * pdB2;
        const int selA = BETTER(keyA2, bk1, keyA1, bk0) ? bk1 : bk0;
        const int selB = BETTER(keyB2, ck1, keyB1, ck0) ? ck1 : ck0;

        if (q == 0) {
            outIdx[(size_t)(bA * NCBK + i) * TSEQQ + tlA] = (float)selA;
            outIdx[(size_t)(bB * NCBK + i) * TSEQQ + tlB] = (float)selB;
        }

        // ---- gather q, write z_q, residual update + re-round ----
        const float* qp0 = cbi + (size_t)selA * CDIM;
        const float* qp1 = cbi + (size_t)selB * CDIM;
        float* zqA = outZq + (size_t)tokA * DDIM + i * CDIM;
        float* zqB = outZq + (size_t)tokB * DDIM + i * CDIM;
        float nr0 = 0.f, nr1 = 0.f;
        #pragma unroll
        for (int m = 0; m < 16; m++) {
            const int d = 4 * m + q, ks = m >> 1, p = (m & 1) * 2;
            const float q0 = __ldg(qp0 + d), q1 = __ldg(qp1 + d);
            zqA[d] = q0; zqB[d] = q1;
            if (i < NCBK - 1) {
                const float vA = zA[(i + 1) * CDIM + d] + ares[ks][p] - q0;
                const float vB = zB[(i + 1) * CDIM + d] + ares[ks][p + 1] - q1;
                nr0 += vA * vA; nr1 += vB * vB;
                ares[ks][p]     = vA;
                ares[ks][p + 1] = vB;
                ahi[ks][p]      = f2tff(vA);
                ahi[ks][p + 1]  = f2tff(vB);
            }
        }
        if (i < NCBK - 1) {
            nr0 += __shfl_xor_sync(0xffffffffu, nr0, 1);
            nr0 += __shfl_xor_sync(0xffffffffu, nr0, 2);
            nr1 += __shfl_xor_sync(0xffffffffu, nr1, 1);
            nr1 += __shfl_xor_sync(0xffffffffu, nr1, 2);
            rn0 = nr0; rn1 = nr1;
        }
    }
}

extern "C" void kernel_launch(void* const* d_in, const int* in_sizes, int n_in,
                              void* d_out, int out_size) {
    const float* z      = (const float*)d_in[0];   // (8, 2048, 512) f32
    const float* cbooks = (const float*)d_in[1];   // (8, 1024, 64)  f32

    float* outZq     = (float*)d_out;
    float* outIdx    = outZq + (size_t)NTOKN * DDIM;
    float* outLogits = outIdx + (size_t)NCBK * NTOKN;

    cudaFuncSetAttribute(rvq_main, cudaFuncAttributeMaxDynamicSharedMemorySize, SM_TOTAL);

    prep<<<TOTCH * 4, 256>>>(cbooks);
    rvq_main<<<NTOKN / MT, THREADS, SM_TOTAL>>>(z, cbooks, outZq, outIdx, outLogits);
}